// round 13
// baseline (speedup 1.0000x reference)
#include <cuda_runtime.h>
#include <math.h>

#define VOL    110592   // 48*48*48
#define HV     55296    // VOL/2
#define PLANE  2304     // 48*48
#define NVOX   221184   // B * VOL
#define NPAIR  110592   // NVOX/2
#define TOTALE 884736   // B*C*VOL
#define U16INF 50000
#define NTASK  384      // 8 * 48 plane tasks per pass
#define GRID   148      // one block per SM -> co-resident, barrier-safe
#define NTHR   384

// Static scratch (no allocations allowed)
__device__ unsigned short g_bufS1[8 * VOL];
__device__ unsigned short g_bufS2[8 * VOL];
__device__ float  g_lut[65536];
__device__ int    g_flags[8];    // zero-init; reset by epilogue each replay
__device__ int    g_count;       // zero-init; reset by epilogue
__device__ int    g_bar1, g_bar2;// zero-init; reset by epilogue
__device__ double g_partials[GRID];

// psq table: entry ((j*8 + grp)*4 + kk), kk<3 used: x0 = grp*6 + 2*kk;
// packed ( (x0-j)^2 , (x0+1-j)^2 )
__device__ __forceinline__ void fill_psq(unsigned int* psq, int tid) {
    for (int i = tid; i < 48 * 8 * 4; i += NTHR) {
        int j  = i >> 5;
        int g  = (i >> 2) & 7;
        int kk = i & 3;
        unsigned int val = 0;
        if (kk < 3) {
            int x0 = g * 6 + 2 * kk;
            int d0 = x0 - j;
            int d1 = d0 + 1;
            val = (unsigned int)(d0 * d0) | ((unsigned int)(d1 * d1) << 16);
        }
        psq[i] = val;
    }
}

__device__ __forceinline__ void grid_barrier(int* bar) {
    __syncthreads();
    __threadfence();
    if (threadIdx.x == 0) {
        atomicAdd(bar, 1);
        while (*((volatile int*)bar) < GRID) { }
    }
    __syncthreads();
}

// Loss for one voxel: softmax(p) dot (q_c + min_{c'!=c} q_c'), flags applied.
__device__ __forceinline__ float voxel_loss(const float* p, const float* q,
                                            const float* fl) {
    float mx = fmaxf(fmaxf(p[0], p[1]), fmaxf(p[2], p[3]));
    float e0 = __expf(p[0] - mx);
    float e1 = __expf(p[1] - mx);
    float e2 = __expf(p[2] - mx);
    float e3 = __expf(p[3] - mx);
    float inv = __fdividef(1.0f, e0 + e1 + e2 + e3);
    float m01 = fminf(q[0], q[1]), m23 = fminf(q[2], q[3]);
    float s0 = q[0] + fminf(q[1], m23);
    float s1 = q[1] + fminf(q[0], m23);
    float s2 = q[2] + fminf(m01, q[3]);
    float s3 = q[3] + fminf(m01, q[2]);
    return (fl[0] * e0 * s0 + fl[1] * e1 * s1
          + fl[2] * e2 * s2 + fl[3] * e3 * s3) * inv;
}

// ---------------------------------------------------------------------------
// One persistent kernel: phase A (W bit-scan + H DPX min-plus), grid barrier,
// phase B (D DPX min-plus), grid barrier, phase C (fused loss + reduction).
// ALL intra-launch cross-SM data is read via __ldcg (L2-coherent); __ldg only
// for external inputs.
// ---------------------------------------------------------------------------
__global__ void __launch_bounds__(NTHR) kFused(const float* __restrict__ pred,
                                               const void* __restrict__ target,
                                               float* __restrict__ out) {
    __shared__ unsigned long long lmask[48];
    __shared__ unsigned short us[48][50];
    __shared__ unsigned int psq[48 * 8 * 4];
    __shared__ int sbad;
    __shared__ int anyflag;
    __shared__ double sh[NTHR];
    __shared__ int islast;

    const int tid = threadIdx.x;
    const int bid = blockIdx.x;

    fill_psq(psq, tid);
    if (tid == 0) sbad = 0;
    __syncthreads();

    // dtype detection from the first 512 bytes (in-bounds either way).
    if (tid < 64) {
        long long v = ((const long long*)target)[tid];
        if (v < 0 || v > 3) atomicOr(&sbad, 1);
    }
    __syncthreads();
    const bool is64 = (sbad == 0);

    // Blocks 0..15 fill the full-range sqrt LUT (4096 entries each);
    // consumed in phase C (after two grid barriers) via __ldcg.
    if (bid < 16) {
        const int lbase = bid * 4096;
        #pragma unroll
        for (int k = 0; k < 11; k++) {
            int i = tid + k * NTHR;
            if (i < 4096) g_lut[lbase + i] = sqrtf((float)(lbase + i));
        }
    }

    // ---- Phase A: one task = (m = b*4+c, d) plane ----
    const int h_row = tid >> 3;            // 0..47
    const int w0 = (tid & 7) * 6;          // 0,6,..42
    const int grp = tid / 48;              // 0..7
    const int lane = tid - grp * 48;       // 0..47
    const int x0 = grp * 6;

    for (int task = bid; task < NTASK; task += GRID) {
        const int m = task / 48;
        const int d = task - m * 48;
        const int b = m >> 2;
        const int c = m & 3;

        if (tid < 48) lmask[tid] = 0ULL;
        if (tid == 0) anyflag = 0;
        __syncthreads();

        // Thread's 6 contiguous labels -> registers.
        const int ebase = b * VOL + d * PLANE + tid * 6;
        unsigned char lb[6];
        if (is64) {
            const longlong2* tp = (const longlong2*)((const long long*)target + ebase);
            longlong2 v0 = __ldg(&tp[0]);
            longlong2 v1 = __ldg(&tp[1]);
            longlong2 v2 = __ldg(&tp[2]);
            lb[0] = (unsigned char)v0.x; lb[1] = (unsigned char)v0.y;
            lb[2] = (unsigned char)v1.x; lb[3] = (unsigned char)v1.y;
            lb[4] = (unsigned char)v2.x; lb[5] = (unsigned char)v2.y;
        } else {
            const int2* tp = (const int2*)((const int*)target + ebase);
            int2 v0 = __ldg(&tp[0]);
            int2 v1 = __ldg(&tp[1]);
            int2 v2 = __ldg(&tp[2]);
            lb[0] = (unsigned char)v0.x; lb[1] = (unsigned char)v0.y;
            lb[2] = (unsigned char)v1.x; lb[3] = (unsigned char)v1.y;
            lb[4] = (unsigned char)v2.x; lb[5] = (unsigned char)v2.y;
        }
        {
            unsigned long long bits = 0ULL;
            #pragma unroll
            for (int k = 0; k < 6; k++) {
                unsigned long long isc = (unsigned long long)(lb[k] == (unsigned char)c);
                bits |= isc << (w0 + k);
            }
            if (bits) { atomicOr(&lmask[h_row], bits); anyflag = 1; }
        }
        __syncthreads();
        if (tid == 0 && anyflag) atomicOr(&g_flags[m], 1);

        // W-EDT for this thread's own 6 pixels (one mask load).
        {
            unsigned long long mm = lmask[h_row];
            unsigned short wd[6];
            #pragma unroll
            for (int k = 0; k < 6; k++) {
                int ww = w0 + k;
                unsigned long long lowm = mm << (63 - ww);
                unsigned long long him  = mm >> ww;
                int dl = lowm ? __clzll(lowm) : 99;
                int dr = him ? (__ffsll(him) - 1) : 99;
                int dd = min(dl, dr);
                wd[k] = (dd <= 47) ? (unsigned short)(dd * dd)
                                   : (unsigned short)U16INF;
            }
            unsigned int* dst = (unsigned int*)&us[h_row][w0];
            dst[0] = (unsigned int)wd[0] | ((unsigned int)wd[1] << 16);
            dst[1] = (unsigned int)wd[2] | ((unsigned int)wd[3] << 16);
            dst[2] = (unsigned int)wd[4] | ((unsigned int)wd[5] << 16);
        }
        __syncthreads();

        // H min-plus via DPX.
        unsigned int a0 = 0xFFFFFFFFu, a1 = 0xFFFFFFFFu, a2 = 0xFFFFFFFFu;
        #pragma unroll
        for (int j = 0; j < 48; j++) {
            unsigned int fj2 = (unsigned int)us[j][lane] * 0x00010001u;
            uint4 q = *(const uint4*)&psq[(j * 8 + grp) * 4];
            a0 = __viaddmin_u16x2(fj2, q.x, a0);
            a1 = __viaddmin_u16x2(fj2, q.y, a1);
            a2 = __viaddmin_u16x2(fj2, q.z, a2);
        }
        const int base = m * VOL + d * PLANE;
        g_bufS1[base + x0 * 48 + lane]       = (unsigned short)(a0 & 0xFFFFu);
        g_bufS1[base + (x0 + 1) * 48 + lane] = (unsigned short)(a0 >> 16);
        g_bufS1[base + (x0 + 2) * 48 + lane] = (unsigned short)(a1 & 0xFFFFu);
        g_bufS1[base + (x0 + 3) * 48 + lane] = (unsigned short)(a1 >> 16);
        g_bufS1[base + (x0 + 4) * 48 + lane] = (unsigned short)(a2 & 0xFFFFu);
        g_bufS1[base + (x0 + 5) * 48 + lane] = (unsigned short)(a2 >> 16);
        __syncthreads();
    }

    grid_barrier(&g_bar1);

    // ---- Phase B: one task = (m, h) plane over (d, w); __ldcg reads ----
    for (int task = bid; task < NTASK; task += GRID) {
        const int m = task / 48;
        const int h = task - m * 48;
        const int base = m * VOL + h * 48;

        const unsigned int* src = (const unsigned int*)(g_bufS1 + base);
        #pragma unroll
        for (int k = 0; k < 3; k++) {
            int p = tid + k * NTHR;        // pair index 0..1151
            int dd = p / 24;
            int wp = p - dd * 24;
            *(unsigned int*)&us[dd][wp * 2] = __ldcg(&src[dd * (PLANE / 2) + wp]);
        }
        __syncthreads();

        unsigned int a0 = 0xFFFFFFFFu, a1 = 0xFFFFFFFFu, a2 = 0xFFFFFFFFu;
        #pragma unroll
        for (int j = 0; j < 48; j++) {
            unsigned int fj2 = (unsigned int)us[j][lane] * 0x00010001u;
            uint4 q = *(const uint4*)&psq[(j * 8 + grp) * 4];
            a0 = __viaddmin_u16x2(fj2, q.x, a0);
            a1 = __viaddmin_u16x2(fj2, q.y, a1);
            a2 = __viaddmin_u16x2(fj2, q.z, a2);
        }
        g_bufS2[base + x0 * PLANE + lane]       = (unsigned short)(a0 & 0xFFFFu);
        g_bufS2[base + (x0 + 1) * PLANE + lane] = (unsigned short)(a0 >> 16);
        g_bufS2[base + (x0 + 2) * PLANE + lane] = (unsigned short)(a1 & 0xFFFFu);
        g_bufS2[base + (x0 + 3) * PLANE + lane] = (unsigned short)(a1 >> 16);
        g_bufS2[base + (x0 + 4) * PLANE + lane] = (unsigned short)(a2 & 0xFFFFu);
        g_bufS2[base + (x0 + 5) * PLANE + lane] = (unsigned short)(a2 >> 16);
        __syncthreads();
    }

    grid_barrier(&g_bar2);

    // ---- Phase C: loss. Two pair-slots/thread, __ldcg for bufS2/lut/flags.
    const float2*  p2 = (const float2*)pred;
    const ushort2* q2 = (const ushort2*)g_bufS2;

    const int t0 = bid * NTHR + tid;        // 0..56831
    const int t1 = t0 + GRID * NTHR;        // may be >= NPAIR
    const bool v1 = (t1 < NPAIR);

    const int b0 = t0 / HV, r0 = t0 - b0 * HV;
    const int bb1 = v1 ? (t1 / HV) : 0;
    const int r1 = v1 ? (t1 - bb1 * HV) : 0;
    const int base0 = b0 * 4 * HV + r0;
    const int base1 = bb1 * 4 * HV + r1;

    float2  P0[4], P1[4];
    ushort2 D0[4], D1[4];
    #pragma unroll
    for (int c = 0; c < 4; c++) P0[c] = __ldg(&p2[base0 + c * HV]);
    #pragma unroll
    for (int c = 0; c < 4; c++) D0[c] = __ldcg((ushort2*)&q2[base0 + c * HV]);
    #pragma unroll
    for (int c = 0; c < 4; c++) P1[c] = v1 ? __ldg(&p2[base1 + c * HV]) : make_float2(0.f, 0.f);
    #pragma unroll
    for (int c = 0; c < 4; c++) D1[c] = v1 ? __ldcg((ushort2*)&q2[base1 + c * HV]) : make_ushort2(0, 0);

    float fl0[4], fl1[4];
    #pragma unroll
    for (int c = 0; c < 4; c++) {
        fl0[c] = __ldcg(&g_flags[b0 * 4 + c]) ? 1.0f : 0.0f;
        fl1[c] = (v1 && __ldcg(&g_flags[bb1 * 4 + c])) ? 1.0f : 0.0f;
    }

    double sum = 0.0;
    {
        float p[4], q[4];
        #pragma unroll
        for (int c = 0; c < 4; c++) { p[c] = P0[c].x; q[c] = __ldcg(&g_lut[D0[c].x]); }
        sum += (double)voxel_loss(p, q, fl0);
        #pragma unroll
        for (int c = 0; c < 4; c++) { p[c] = P0[c].y; q[c] = __ldcg(&g_lut[D0[c].y]); }
        sum += (double)voxel_loss(p, q, fl0);
        if (v1) {
            #pragma unroll
            for (int c = 0; c < 4; c++) { p[c] = P1[c].x; q[c] = __ldcg(&g_lut[D1[c].x]); }
            sum += (double)voxel_loss(p, q, fl1);
            #pragma unroll
            for (int c = 0; c < 4; c++) { p[c] = P1[c].y; q[c] = __ldcg(&g_lut[D1[c].y]); }
            sum += (double)voxel_loss(p, q, fl1);
        }
    }

    // Block reduction: 384 -> 128 (3-way) -> tree.
    sh[tid] = sum;
    __syncthreads();
    if (tid < 128) sh[tid] += sh[tid + 128] + sh[tid + 256];
    __syncthreads();
    #pragma unroll
    for (int st = 64; st > 0; st >>= 1) {
        if (tid < st) sh[tid] += sh[tid + st];
        __syncthreads();
    }
    if (tid == 0) {
        g_partials[bid] = sh[0];
        __threadfence();
        int done = atomicAdd(&g_count, 1);
        islast = (done == GRID - 1);
    }
    __syncthreads();

    if (islast) {
        if (tid < 256) sh[tid] = (tid < GRID) ? __ldcg(&g_partials[tid]) : 0.0;
        __syncthreads();
        #pragma unroll
        for (int st = 128; st > 0; st >>= 1) {
            if (tid < st) sh[tid] += sh[tid + st];
            __syncthreads();
        }
        if (tid == 0) {
            out[0] = (float)(sh[0] / (double)TOTALE);
            g_count = 0;      // reset for next graph replay
            g_bar1 = 0;
            g_bar2 = 0;
        }
        if (tid < 8) g_flags[tid] = 0;
    }
}

// ---------------------------------------------------------------------------
extern "C" void kernel_launch(void* const* d_in, const int* in_sizes, int n_in,
                              void* d_out, int out_size) {
    const float* pred   = (const float*)d_in[0];
    const void*  target = d_in[1];
    float* out = (float*)d_out;

    kFused<<<GRID, NTHR>>>(pred, target, out);
}

// round 14
// speedup vs baseline: 1.2545x; 1.2545x over previous
#include <cuda_runtime.h>
#include <math.h>

#define VOL    110592   // 48*48*48
#define HV     55296    // VOL/2
#define PLANE  2304     // 48*48
#define NVOX   221184   // B * VOL
#define TOTALE 884736   // B*C*VOL
#define U16INF 50000    // u16 'infinity'; max transient 50000+2209 < 65535
#define LOSSBLKS 432    // NVOX / 2 / 256

// Static scratch (no allocations allowed)
__device__ unsigned short g_bufS1[8 * VOL];  // pos^2 after W+H (u16)
__device__ unsigned short g_bufS2[8 * VOL];  // pos^2 after W+H+D (u16)
__device__ float  g_lut[65536];              // sqrt LUT, full u16 range
__device__ int    g_flags[8];   // zero-init; reset by loss epilogue each replay
__device__ int    g_count;      // zero-init; reset by loss epilogue
__device__ double g_partials[LOSSBLKS];

// psqb table: entry ((j*16 + g16)*4 + kk), kk<3 used: x = g16*3 + kk;
// value = (x-j)^2 broadcast into both u16 halves. 48*16*4 u32 = 12 KB.
__device__ __forceinline__ void fill_psqb(unsigned int* psqb, int tid) {
    for (int i = tid; i < 48 * 16 * 4; i += 384) {
        int j   = i >> 6;
        int g16 = (i >> 2) & 15;
        int kk  = i & 3;
        unsigned int val = 0;
        if (kk < 3) {
            int dx = g16 * 3 + kk - j;
            val = (unsigned int)(dx * dx) * 0x00010001u;
        }
        psqb[i] = val;
    }
}

// ---------------------------------------------------------------------------
// Kernel A: one block per (m=b*4+c, d) plane, 384 threads.
// Register-direct label loads, class line masks, exact W-EDT via clz/ffs
// (packed u16x2 rows), exact H min-plus via lane-pair DPX.
// Blocks 0..15 fill the sqrt LUT.
// ---------------------------------------------------------------------------
__global__ void __launch_bounds__(384) kA(const void* __restrict__ target) {
    __shared__ unsigned long long lmask[48];
    __shared__ unsigned int usrow[48][25];   // row j: 24 packed lane-pairs + pad
    __shared__ unsigned int psqb[48 * 16 * 4];
    __shared__ int sbad;
    __shared__ int anyflag;

    const int tid = threadIdx.x;
    const int m = blockIdx.x / 48;        // b*4 + c
    const int d = blockIdx.x - m * 48;
    const int b = m >> 2;
    const int c = m & 3;

    if (tid < 48) lmask[tid] = 0ULL;
    if (tid == 0) { sbad = 0; anyflag = 0; }
    fill_psqb(psqb, tid);
    __syncthreads();

    // dtype detection from the first 512 bytes (in-bounds either way).
    if (tid < 64) {
        long long v = ((const long long*)target)[tid];
        if (v < 0 || v > 3) atomicOr(&sbad, 1);
    }
    __syncthreads();
    const bool is64 = (sbad == 0);

    // Thread's 6 contiguous labels -> registers.
    const int ebase = b * VOL + d * PLANE + tid * 6;
    unsigned char lb[6];
    if (is64) {
        const longlong2* tp = (const longlong2*)((const long long*)target + ebase);
        longlong2 v0 = __ldg(&tp[0]);
        longlong2 v1 = __ldg(&tp[1]);
        longlong2 v2 = __ldg(&tp[2]);
        lb[0] = (unsigned char)v0.x; lb[1] = (unsigned char)v0.y;
        lb[2] = (unsigned char)v1.x; lb[3] = (unsigned char)v1.y;
        lb[4] = (unsigned char)v2.x; lb[5] = (unsigned char)v2.y;
    } else {
        const int2* tp = (const int2*)((const int*)target + ebase);
        int2 v0 = __ldg(&tp[0]);
        int2 v1 = __ldg(&tp[1]);
        int2 v2 = __ldg(&tp[2]);
        lb[0] = (unsigned char)v0.x; lb[1] = (unsigned char)v0.y;
        lb[2] = (unsigned char)v1.x; lb[3] = (unsigned char)v1.y;
        lb[4] = (unsigned char)v2.x; lb[5] = (unsigned char)v2.y;
    }

    // Mask chunk: h = tid/8, w0 = (tid%8)*6.
    const int h_row = tid >> 3;
    const int w0 = (tid & 7) * 6;
    {
        unsigned long long bits = 0ULL;
        #pragma unroll
        for (int k = 0; k < 6; k++) {
            unsigned long long isc = (unsigned long long)(lb[k] == (unsigned char)c);
            bits |= isc << (w0 + k);
        }
        if (bits) { atomicOr(&lmask[h_row], bits); anyflag = 1; }
    }

    // Blocks 0..15 fill the full-range sqrt LUT (4096 entries each).
    if (blockIdx.x < 16) {
        const int lbase = blockIdx.x * 4096;
        #pragma unroll
        for (int k = 0; k < 11; k++) {
            int i = tid + k * 384;
            if (i < 4096) g_lut[lbase + i] = sqrtf((float)(lbase + i));
        }
    }
    __syncthreads();
    if (tid == 0 && anyflag) atomicOr(&g_flags[m], 1);

    // W-EDT for the thread's own 6 pixels; pack into u32 row pairs.
    {
        unsigned long long mm = lmask[h_row];
        unsigned short wd[6];
        #pragma unroll
        for (int k = 0; k < 6; k++) {
            int ww = w0 + k;
            unsigned long long lowm = mm << (63 - ww);
            unsigned long long him  = mm >> ww;
            int dl = lowm ? __clzll(lowm) : 99;
            int dr = him ? (__ffsll(him) - 1) : 99;
            int dd = min(dl, dr);
            wd[k] = (dd <= 47) ? (unsigned short)(dd * dd)
                               : (unsigned short)U16INF;
        }
        const int p0 = (tid & 7) * 3;   // w0/2
        usrow[h_row][p0]     = (unsigned int)wd[0] | ((unsigned int)wd[1] << 16);
        usrow[h_row][p0 + 1] = (unsigned int)wd[2] | ((unsigned int)wd[3] << 16);
        usrow[h_row][p0 + 2] = (unsigned int)wd[4] | ((unsigned int)wd[5] << 16);
    }
    __syncthreads();

    // H min-plus via lane-pair DPX: p = lane pair (w=2p, 2p+1), g16 owns
    // x in [g16*3, g16*3+3).
    const int p = tid % 24;
    const int g16 = tid / 24;
    unsigned int a0 = 0xFFFFFFFFu, a1 = 0xFFFFFFFFu, a2 = 0xFFFFFFFFu;

    #pragma unroll
    for (int j = 0; j < 48; j++) {
        unsigned int fj2 = usrow[j][p];
        uint4 q = *(const uint4*)&psqb[(j * 16 + g16) * 4];
        a0 = __viaddmin_u16x2(fj2, q.x, a0);
        a1 = __viaddmin_u16x2(fj2, q.y, a1);
        a2 = __viaddmin_u16x2(fj2, q.z, a2);
    }

    const int base = m * VOL + d * PLANE;
    const int x0 = g16 * 3;
    *(unsigned int*)&g_bufS1[base + x0 * 48 + 2 * p]       = a0;
    *(unsigned int*)&g_bufS1[base + (x0 + 1) * 48 + 2 * p] = a1;
    *(unsigned int*)&g_bufS1[base + (x0 + 2) * 48 + 2 * p] = a2;
}

// ---------------------------------------------------------------------------
// Kernel B: exact D min-plus via lane-pair DPX. One block per (m, h) plane
// (rows = d, cols = w), 384 threads.
// ---------------------------------------------------------------------------
__global__ void __launch_bounds__(384) kB() {
    __shared__ unsigned int usrow[48][25];
    __shared__ unsigned int psqb[48 * 16 * 4];

    const int tid = threadIdx.x;
    const int m = blockIdx.x / 48;
    const int h = blockIdx.x - m * 48;
    const int base = m * VOL + h * 48;

    fill_psqb(psqb, tid);

    // Load plane rows as packed u32 pairs (1152 words, 3 per thread).
    {
        const unsigned int* src = (const unsigned int*)(g_bufS1 + base);
        #pragma unroll
        for (int k = 0; k < 3; k++) {
            int i = tid + k * 384;          // pair index 0..1151
            int dd = i / 24;
            int wp = i - dd * 24;
            usrow[dd][wp] = src[dd * (PLANE / 2) + wp];
        }
    }
    __syncthreads();

    const int p = tid % 24;
    const int g16 = tid / 24;
    unsigned int a0 = 0xFFFFFFFFu, a1 = 0xFFFFFFFFu, a2 = 0xFFFFFFFFu;

    #pragma unroll
    for (int j = 0; j < 48; j++) {
        unsigned int fj2 = usrow[j][p];
        uint4 q = *(const uint4*)&psqb[(j * 16 + g16) * 4];
        a0 = __viaddmin_u16x2(fj2, q.x, a0);
        a1 = __viaddmin_u16x2(fj2, q.y, a1);
        a2 = __viaddmin_u16x2(fj2, q.z, a2);
    }

    const int x0 = g16 * 3;
    *(unsigned int*)&g_bufS2[base + x0 * PLANE + 2 * p]       = a0;
    *(unsigned int*)&g_bufS2[base + (x0 + 1) * PLANE + 2 * p] = a1;
    *(unsigned int*)&g_bufS2[base + (x0 + 2) * PLANE + 2 * p] = a2;
}

// ---------------------------------------------------------------------------
// Loss: 2 voxels/thread (float2 pred, ushort2 dist, front-batched MLP=8).
// q_c = LUT[pos2_c] (full-range, branch-free); |sdf_c| = q_c + min_{c'!=c}.
// Deterministic double reduction; last block finishes + resets globals.
// ---------------------------------------------------------------------------
__global__ void __launch_bounds__(256) k_loss(const float* __restrict__ pred,
                                              float* __restrict__ out) {
    const int t = blockIdx.x * 256 + threadIdx.x;   // 0..110591
    const int b = t / HV;
    const int r = t - b * HV;
    const int base2 = b * 4 * HV + r;

    const float2*  p2 = (const float2*)pred;
    const ushort2* q2 = (const ushort2*)g_bufS2;

    float2  P[4];
    ushort2 Dv[4];
    #pragma unroll
    for (int c = 0; c < 4; c++) P[c] = __ldg(&p2[base2 + c * HV]);
    #pragma unroll
    for (int c = 0; c < 4; c++) Dv[c] = __ldg(&q2[base2 + c * HV]);

    float fl[4];
    #pragma unroll
    for (int c = 0; c < 4; c++) fl[c] = g_flags[b * 4 + c] ? 1.0f : 0.0f;

    double sum = 0.0;
    #pragma unroll
    for (int v = 0; v < 2; v++) {
        float p0 = v ? P[0].y : P[0].x;
        float p1 = v ? P[1].y : P[1].x;
        float p2v = v ? P[2].y : P[2].x;
        float p3 = v ? P[3].y : P[3].x;
        int i0 = v ? Dv[0].y : Dv[0].x;
        int i1 = v ? Dv[1].y : Dv[1].x;
        int i2 = v ? Dv[2].y : Dv[2].x;
        int i3 = v ? Dv[3].y : Dv[3].x;

        float q0 = __ldg(&g_lut[i0]);
        float q1 = __ldg(&g_lut[i1]);
        float q2c = __ldg(&g_lut[i2]);
        float q3 = __ldg(&g_lut[i3]);

        float mx = fmaxf(fmaxf(p0, p1), fmaxf(p2v, p3));
        float e0 = __expf(p0 - mx);
        float e1 = __expf(p1 - mx);
        float e2 = __expf(p2v - mx);
        float e3 = __expf(p3 - mx);
        float inv = __fdividef(1.0f, e0 + e1 + e2 + e3);

        float m01 = fminf(q0, q1), m23 = fminf(q2c, q3);
        float s0 = q0 + fminf(q1, m23);
        float s1 = q1 + fminf(q0, m23);
        float s2 = q2c + fminf(m01, q3);
        float s3 = q3 + fminf(m01, q2c);

        float local = fl[0] * e0 * s0 + fl[1] * e1 * s1
                    + fl[2] * e2 * s2 + fl[3] * e3 * s3;
        sum += (double)(local * inv);
    }

    __shared__ double sh[256];
    __shared__ int islast;
    sh[threadIdx.x] = sum;
    __syncthreads();
    #pragma unroll
    for (int st = 128; st > 0; st >>= 1) {
        if (threadIdx.x < st) sh[threadIdx.x] += sh[threadIdx.x + st];
        __syncthreads();
    }
    if (threadIdx.x == 0) {
        g_partials[blockIdx.x] = sh[0];
        __threadfence();
        int done = atomicAdd(&g_count, 1);
        islast = (done == gridDim.x - 1);
    }
    __syncthreads();

    if (islast) {
        int i2n = threadIdx.x + 256;
        double v = g_partials[threadIdx.x]
                 + ((i2n < LOSSBLKS) ? g_partials[i2n] : 0.0);
        sh[threadIdx.x] = v;
        __syncthreads();
        #pragma unroll
        for (int st = 128; st > 0; st >>= 1) {
            if (threadIdx.x < st) sh[threadIdx.x] += sh[threadIdx.x + st];
            __syncthreads();
        }
        if (threadIdx.x == 0) {
            out[0] = (float)(sh[0] / (double)TOTALE);
            g_count = 0;                    // reset for next graph replay
        }
        if (threadIdx.x < 8) g_flags[threadIdx.x] = 0;
    }
}

// ---------------------------------------------------------------------------
extern "C" void kernel_launch(void* const* d_in, const int* in_sizes, int n_in,
                              void* d_out, int out_size) {
    const float* pred   = (const float*)d_in[0];
    const void*  target = d_in[1];
    float* out = (float*)d_out;

    kA<<<8 * 48, 384>>>(target);        // W bit-scan + H lane-pair DPX
    kB<<<8 * 48, 384>>>();              // D lane-pair DPX
    k_loss<<<LOSSBLKS, 256>>>(pred, out);
}

// round 15
// speedup vs baseline: 1.2667x; 1.0097x over previous
#include <cuda_runtime.h>
#include <math.h>

#define VOL    110592   // 48*48*48
#define HV     55296    // VOL/2
#define PLANE  2304     // 48*48
#define NVOX   221184   // B * VOL
#define TOTALE 884736   // B*C*VOL
#define U16INF 50000    // u16 'infinity'; max transient 50000+2209 < 65535
#define LOSSBLKS 432    // NVOX / 2 / 256

// Static scratch (no allocations allowed)
__device__ unsigned short g_bufS1[8 * VOL];  // pos^2 after W+H (u16)
__device__ unsigned short g_bufS2[8 * VOL];  // pos^2 after W+H+D (u16)
__device__ float  g_lut[65536];              // sqrt LUT, full u16 range
__device__ int    g_flags[8];   // zero-init; reset by loss epilogue each replay
__device__ int    g_count;      // zero-init; reset by loss epilogue
__device__ double g_partials[LOSSBLKS];

// psqb table: entry ((j*16 + g16)*4 + kk), kk<3 used: x = g16*3 + kk;
// value = (x-j)^2 broadcast into both u16 halves. 48*16*4 u32 = 12 KB.
__device__ __forceinline__ void fill_psqb(unsigned int* psqb, int tid) {
    for (int i = tid; i < 48 * 16 * 4; i += 384) {
        int j   = i >> 6;
        int g16 = (i >> 2) & 15;
        int kk  = i & 3;
        unsigned int val = 0;
        if (kk < 3) {
            int dx = g16 * 3 + kk - j;
            val = (unsigned int)(dx * dx) * 0x00010001u;
        }
        psqb[i] = val;
    }
}

// ---------------------------------------------------------------------------
// Kernel A: one block per (m=b*4+c, d) plane, 384 threads, TWO barriers.
// Speculative int32 label load at cycle 0; dtype detect overlapped with the
// psqb/LUT fill and resolved by __syncthreads_or; row masks via shfl_xor
// (no smem, no atomics); W-EDT; presence flag via second __syncthreads_or
// (doubles as the pre-H barrier); H min-plus via lane-pair DPX.
// ---------------------------------------------------------------------------
__global__ void __launch_bounds__(384) kA(const void* __restrict__ target) {
    __shared__ unsigned int usrow[48][25];   // row j: 24 packed lane-pairs + pad
    __shared__ unsigned int psqb[48 * 16 * 4];

    const int tid = threadIdx.x;
    const int m = blockIdx.x / 48;        // b*4 + c
    const int d = blockIdx.x - m * 48;
    const int b = m >> 2;
    const int c = m & 3;
    const int ebase = b * VOL + d * PLANE + tid * 6;

    // Speculative int32 label load (in-bounds for both dtypes), issued first.
    const int2* tp32 = (const int2*)((const int*)target + ebase);
    int2 s0 = __ldg(&tp32[0]);
    int2 s1 = __ldg(&tp32[1]);
    int2 s2 = __ldg(&tp32[2]);

    // dtype detect predicate (first 512 bytes, in-bounds either way).
    bool bad = false;
    if (tid < 64) {
        long long v = ((const long long*)target)[tid];
        bad = (v < 0 || v > 3);
    }

    fill_psqb(psqb, tid);

    // Blocks 0..15 fill the full-range sqrt LUT (consumed by k_loss).
    if (blockIdx.x < 16) {
        const int lbase = blockIdx.x * 4096;
        #pragma unroll
        for (int k = 0; k < 11; k++) {
            int i = tid + k * 384;
            if (i < 4096) g_lut[lbase + i] = sqrtf((float)(lbase + i));
        }
    }

    // Barrier 1: resolves dtype AND covers the psqb fill.
    const bool is64 = !__syncthreads_or((int)bad);

    unsigned char lb[6];
    if (is64) {
        const longlong2* tp = (const longlong2*)((const long long*)target + ebase);
        longlong2 v0 = __ldg(&tp[0]);
        longlong2 v1 = __ldg(&tp[1]);
        longlong2 v2 = __ldg(&tp[2]);
        lb[0] = (unsigned char)v0.x; lb[1] = (unsigned char)v0.y;
        lb[2] = (unsigned char)v1.x; lb[3] = (unsigned char)v1.y;
        lb[4] = (unsigned char)v2.x; lb[5] = (unsigned char)v2.y;
    } else {
        lb[0] = (unsigned char)s0.x; lb[1] = (unsigned char)s0.y;
        lb[2] = (unsigned char)s1.x; lb[3] = (unsigned char)s1.y;
        lb[4] = (unsigned char)s2.x; lb[5] = (unsigned char)s2.y;
    }

    // Build 6-bit chunk; full row mask via 3 shfl_xor rounds over the 8
    // lane-aligned threads of this row (h = tid/8, w0 = (tid%8)*6).
    const int w0 = (tid & 7) * 6;
    unsigned long long bits = 0ULL;
    #pragma unroll
    for (int k = 0; k < 6; k++) {
        unsigned long long isc = (unsigned long long)(lb[k] == (unsigned char)c);
        bits |= isc << (w0 + k);
    }
    unsigned long long mm = bits;
    mm |= __shfl_xor_sync(0xffffffffu, mm, 1, 8);
    mm |= __shfl_xor_sync(0xffffffffu, mm, 2, 8);
    mm |= __shfl_xor_sync(0xffffffffu, mm, 4, 8);

    // W-EDT for this thread's 6 pixels from the register row mask.
    {
        unsigned short wd[6];
        #pragma unroll
        for (int k = 0; k < 6; k++) {
            int ww = w0 + k;
            unsigned long long lowm = mm << (63 - ww);
            unsigned long long him  = mm >> ww;
            int dl = lowm ? __clzll(lowm) : 99;
            int dr = him ? (__ffsll(him) - 1) : 99;
            int dd = min(dl, dr);
            wd[k] = (dd <= 47) ? (unsigned short)(dd * dd)
                               : (unsigned short)U16INF;
        }
        const int h_row = tid >> 3;
        const int p0 = (tid & 7) * 3;
        usrow[h_row][p0]     = (unsigned int)wd[0] | ((unsigned int)wd[1] << 16);
        usrow[h_row][p0 + 1] = (unsigned int)wd[2] | ((unsigned int)wd[3] << 16);
        usrow[h_row][p0 + 2] = (unsigned int)wd[4] | ((unsigned int)wd[5] << 16);
    }

    // Barrier 2: presence flag AND the pre-H usrow barrier in one.
    const int any = __syncthreads_or((int)(bits != 0ULL));
    if (tid == 0 && any) atomicOr(&g_flags[m], 1);

    // H min-plus via lane-pair DPX: p = lane pair (w=2p,2p+1); g16 owns
    // x in [g16*3, g16*3+3).
    const int p = tid % 24;
    const int g16 = tid / 24;
    unsigned int a0 = 0xFFFFFFFFu, a1 = 0xFFFFFFFFu, a2 = 0xFFFFFFFFu;

    #pragma unroll
    for (int j = 0; j < 48; j++) {
        unsigned int fj2 = usrow[j][p];
        uint4 q = *(const uint4*)&psqb[(j * 16 + g16) * 4];
        a0 = __viaddmin_u16x2(fj2, q.x, a0);
        a1 = __viaddmin_u16x2(fj2, q.y, a1);
        a2 = __viaddmin_u16x2(fj2, q.z, a2);
    }

    const int base = m * VOL + d * PLANE;
    const int x0 = g16 * 3;
    *(unsigned int*)&g_bufS1[base + x0 * 48 + 2 * p]       = a0;
    *(unsigned int*)&g_bufS1[base + (x0 + 1) * 48 + 2 * p] = a1;
    *(unsigned int*)&g_bufS1[base + (x0 + 2) * 48 + 2 * p] = a2;
}

// ---------------------------------------------------------------------------
// Kernel B: exact D min-plus via lane-pair DPX. One block per (m, h) plane
// (rows = d, cols = w), 384 threads. Global loads issued before the psq fill.
// ---------------------------------------------------------------------------
__global__ void __launch_bounds__(384) kB() {
    __shared__ unsigned int usrow[48][25];
    __shared__ unsigned int psqb[48 * 16 * 4];

    const int tid = threadIdx.x;
    const int m = blockIdx.x / 48;
    const int h = blockIdx.x - m * 48;
    const int base = m * VOL + h * 48;

    // Issue the 3 plane loads first (latency hidden behind the psq fill).
    const unsigned int* src = (const unsigned int*)(g_bufS1 + base);
    unsigned int r0, r1, r2;
    int dd0, wp0, dd1, wp1, dd2, wp2;
    {
        int i0 = tid;          dd0 = i0 / 24; wp0 = i0 - dd0 * 24;
        int i1 = tid + 384;    dd1 = i1 / 24; wp1 = i1 - dd1 * 24;
        int i2 = tid + 768;    dd2 = i2 / 24; wp2 = i2 - dd2 * 24;
        r0 = __ldg(&src[dd0 * (PLANE / 2) + wp0]);
        r1 = __ldg(&src[dd1 * (PLANE / 2) + wp1]);
        r2 = __ldg(&src[dd2 * (PLANE / 2) + wp2]);
    }

    fill_psqb(psqb, tid);

    usrow[dd0][wp0] = r0;
    usrow[dd1][wp1] = r1;
    usrow[dd2][wp2] = r2;
    __syncthreads();

    const int p = tid % 24;
    const int g16 = tid / 24;
    unsigned int a0 = 0xFFFFFFFFu, a1 = 0xFFFFFFFFu, a2 = 0xFFFFFFFFu;

    #pragma unroll
    for (int j = 0; j < 48; j++) {
        unsigned int fj2 = usrow[j][p];
        uint4 q = *(const uint4*)&psqb[(j * 16 + g16) * 4];
        a0 = __viaddmin_u16x2(fj2, q.x, a0);
        a1 = __viaddmin_u16x2(fj2, q.y, a1);
        a2 = __viaddmin_u16x2(fj2, q.z, a2);
    }

    const int x0 = g16 * 3;
    *(unsigned int*)&g_bufS2[base + x0 * PLANE + 2 * p]       = a0;
    *(unsigned int*)&g_bufS2[base + (x0 + 1) * PLANE + 2 * p] = a1;
    *(unsigned int*)&g_bufS2[base + (x0 + 2) * PLANE + 2 * p] = a2;
}

// ---------------------------------------------------------------------------
// Loss: 2 voxels/thread (float2 pred, ushort2 dist, front-batched MLP=8).
// q_c = LUT[pos2_c] (full-range, branch-free); |sdf_c| = q_c + min_{c'!=c}.
// Deterministic double reduction; last block finishes + resets globals.
// ---------------------------------------------------------------------------
__global__ void __launch_bounds__(256) k_loss(const float* __restrict__ pred,
                                              float* __restrict__ out) {
    const int t = blockIdx.x * 256 + threadIdx.x;   // 0..110591
    const int b = t / HV;
    const int r = t - b * HV;
    const int base2 = b * 4 * HV + r;

    const float2*  p2 = (const float2*)pred;
    const ushort2* q2 = (const ushort2*)g_bufS2;

    float2  P[4];
    ushort2 Dv[4];
    #pragma unroll
    for (int c = 0; c < 4; c++) P[c] = __ldg(&p2[base2 + c * HV]);
    #pragma unroll
    for (int c = 0; c < 4; c++) Dv[c] = __ldg(&q2[base2 + c * HV]);

    float fl[4];
    #pragma unroll
    for (int c = 0; c < 4; c++) fl[c] = g_flags[b * 4 + c] ? 1.0f : 0.0f;

    double sum = 0.0;
    #pragma unroll
    for (int v = 0; v < 2; v++) {
        float p0 = v ? P[0].y : P[0].x;
        float p1 = v ? P[1].y : P[1].x;
        float p2v = v ? P[2].y : P[2].x;
        float p3 = v ? P[3].y : P[3].x;
        int i0 = v ? Dv[0].y : Dv[0].x;
        int i1 = v ? Dv[1].y : Dv[1].x;
        int i2 = v ? Dv[2].y : Dv[2].x;
        int i3 = v ? Dv[3].y : Dv[3].x;

        float q0 = __ldg(&g_lut[i0]);
        float q1 = __ldg(&g_lut[i1]);
        float q2c = __ldg(&g_lut[i2]);
        float q3 = __ldg(&g_lut[i3]);

        float mx = fmaxf(fmaxf(p0, p1), fmaxf(p2v, p3));
        float e0 = __expf(p0 - mx);
        float e1 = __expf(p1 - mx);
        float e2 = __expf(p2v - mx);
        float e3 = __expf(p3 - mx);
        float inv = __fdividef(1.0f, e0 + e1 + e2 + e3);

        float m01 = fminf(q0, q1), m23 = fminf(q2c, q3);
        float s0 = q0 + fminf(q1, m23);
        float s1 = q1 + fminf(q0, m23);
        float s2 = q2c + fminf(m01, q3);
        float s3 = q3 + fminf(m01, q2c);

        float local = fl[0] * e0 * s0 + fl[1] * e1 * s1
                    + fl[2] * e2 * s2 + fl[3] * e3 * s3;
        sum += (double)(local * inv);
    }

    __shared__ double sh[256];
    __shared__ int islast;
    sh[threadIdx.x] = sum;
    __syncthreads();
    #pragma unroll
    for (int st = 128; st > 0; st >>= 1) {
        if (threadIdx.x < st) sh[threadIdx.x] += sh[threadIdx.x + st];
        __syncthreads();
    }
    if (threadIdx.x == 0) {
        g_partials[blockIdx.x] = sh[0];
        __threadfence();
        int done = atomicAdd(&g_count, 1);
        islast = (done == gridDim.x - 1);
    }
    __syncthreads();

    if (islast) {
        int i2n = threadIdx.x + 256;
        double v = g_partials[threadIdx.x]
                 + ((i2n < LOSSBLKS) ? g_partials[i2n] : 0.0);
        sh[threadIdx.x] = v;
        __syncthreads();
        #pragma unroll
        for (int st = 128; st > 0; st >>= 1) {
            if (threadIdx.x < st) sh[threadIdx.x] += sh[threadIdx.x + st];
            __syncthreads();
        }
        if (threadIdx.x == 0) {
            out[0] = (float)(sh[0] / (double)TOTALE);
            g_count = 0;                    // reset for next graph replay
        }
        if (threadIdx.x < 8) g_flags[threadIdx.x] = 0;
    }
}

// ---------------------------------------------------------------------------
extern "C" void kernel_launch(void* const* d_in, const int* in_sizes, int n_in,
                              void* d_out, int out_size) {
    const float* pred   = (const float*)d_in[0];
    const void*  target = d_in[1];
    float* out = (float*)d_out;

    kA<<<8 * 48, 384>>>(target);        // W bit-scan + H lane-pair DPX
    kB<<<8 * 48, 384>>>();              // D lane-pair DPX
    k_loss<<<LOSSBLKS, 256>>>(pred, out);
}

// round 16
// speedup vs baseline: 1.2684x; 1.0014x over previous
#include <cuda_runtime.h>
#include <math.h>

#define VOL    110592   // 48*48*48
#define HV     55296    // VOL/2
#define PLANE  2304     // 48*48
#define NVOX   221184   // B * VOL
#define TOTALE 884736   // B*C*VOL
#define U16INF 50000    // u16 'infinity'; max transient 50000+2209 < 65535
#define LOSSBLKS 432    // NVOX / 2 / 256

// Static scratch (no allocations allowed)
__device__ unsigned short g_bufS1[8 * VOL];  // pos^2 after W+H (u16)
__device__ unsigned short g_bufS2[8 * VOL];  // pos^2 after W+H+D (u16)
__device__ float  g_lut[65536];              // sqrt LUT, full u16 range
__device__ int    g_flags[8];   // zero-init; reset by loss epilogue each replay
__device__ int    g_count;      // zero-init; reset by loss epilogue
__device__ double g_partials[LOSSBLKS];

// psqb table: entry ((j*16 + g16)*4 + kk), kk<3 used: x = g16*3 + kk;
// value = (x-j)^2 broadcast into both u16 halves. 48*16*4 u32 = 12 KB.
__device__ __forceinline__ void fill_psqb(unsigned int* psqb, int tid) {
    for (int i = tid; i < 48 * 16 * 4; i += 384) {
        int j   = i >> 6;
        int g16 = (i >> 2) & 15;
        int kk  = i & 3;
        unsigned int val = 0;
        if (kk < 3) {
            int dx = g16 * 3 + kk - j;
            val = (unsigned int)(dx * dx) * 0x00010001u;
        }
        psqb[i] = val;
    }
}

// ---------------------------------------------------------------------------
// Kernel A: one block per (m=b*4+c, d) plane, 384 threads, two barriers.
// Speculative int32 label load at cycle 0; dtype detect overlapped with the
// psqb/LUT fill; row masks via shfl_xor; W-EDT; H min-plus via lane-pair DPX.
// Triggers PDL completion before its DPX loop so kB's prologue overlaps.
// ---------------------------------------------------------------------------
__global__ void __launch_bounds__(384) kA(const void* __restrict__ target) {
    __shared__ unsigned int usrow[48][25];   // row j: 24 packed lane-pairs + pad
    __shared__ unsigned int psqb[48 * 16 * 4];

    const int tid = threadIdx.x;
    const int m = blockIdx.x / 48;        // b*4 + c
    const int d = blockIdx.x - m * 48;
    const int b = m >> 2;
    const int c = m & 3;
    const int ebase = b * VOL + d * PLANE + tid * 6;

    // Speculative int32 label load (in-bounds for both dtypes), issued first.
    const int2* tp32 = (const int2*)((const int*)target + ebase);
    int2 s0 = __ldg(&tp32[0]);
    int2 s1 = __ldg(&tp32[1]);
    int2 s2 = __ldg(&tp32[2]);

    // dtype detect predicate (first 512 bytes, in-bounds either way).
    bool bad = false;
    if (tid < 64) {
        long long v = ((const long long*)target)[tid];
        bad = (v < 0 || v > 3);
    }

    fill_psqb(psqb, tid);

    // Blocks 0..15 fill the full-range sqrt LUT (consumed by k_loss).
    if (blockIdx.x < 16) {
        const int lbase = blockIdx.x * 4096;
        #pragma unroll
        for (int k = 0; k < 11; k++) {
            int i = tid + k * 384;
            if (i < 4096) g_lut[lbase + i] = sqrtf((float)(lbase + i));
        }
    }

    // Barrier 1: resolves dtype AND covers the psqb fill.
    const bool is64 = !__syncthreads_or((int)bad);

    unsigned char lb[6];
    if (is64) {
        const longlong2* tp = (const longlong2*)((const long long*)target + ebase);
        longlong2 v0 = __ldg(&tp[0]);
        longlong2 v1 = __ldg(&tp[1]);
        longlong2 v2 = __ldg(&tp[2]);
        lb[0] = (unsigned char)v0.x; lb[1] = (unsigned char)v0.y;
        lb[2] = (unsigned char)v1.x; lb[3] = (unsigned char)v1.y;
        lb[4] = (unsigned char)v2.x; lb[5] = (unsigned char)v2.y;
    } else {
        lb[0] = (unsigned char)s0.x; lb[1] = (unsigned char)s0.y;
        lb[2] = (unsigned char)s1.x; lb[3] = (unsigned char)s1.y;
        lb[4] = (unsigned char)s2.x; lb[5] = (unsigned char)s2.y;
    }

    // 6-bit chunk; full row mask via 3 shfl_xor rounds over 8 lane-aligned
    // threads of this row (h = tid/8, w0 = (tid%8)*6).
    const int w0 = (tid & 7) * 6;
    unsigned long long bits = 0ULL;
    #pragma unroll
    for (int k = 0; k < 6; k++) {
        unsigned long long isc = (unsigned long long)(lb[k] == (unsigned char)c);
        bits |= isc << (w0 + k);
    }
    unsigned long long mm = bits;
    mm |= __shfl_xor_sync(0xffffffffu, mm, 1, 8);
    mm |= __shfl_xor_sync(0xffffffffu, mm, 2, 8);
    mm |= __shfl_xor_sync(0xffffffffu, mm, 4, 8);

    // W-EDT for this thread's 6 pixels from the register row mask.
    {
        unsigned short wd[6];
        #pragma unroll
        for (int k = 0; k < 6; k++) {
            int ww = w0 + k;
            unsigned long long lowm = mm << (63 - ww);
            unsigned long long him  = mm >> ww;
            int dl = lowm ? __clzll(lowm) : 99;
            int dr = him ? (__ffsll(him) - 1) : 99;
            int dd = min(dl, dr);
            wd[k] = (dd <= 47) ? (unsigned short)(dd * dd)
                               : (unsigned short)U16INF;
        }
        const int h_row = tid >> 3;
        const int p0 = (tid & 7) * 3;
        usrow[h_row][p0]     = (unsigned int)wd[0] | ((unsigned int)wd[1] << 16);
        usrow[h_row][p0 + 1] = (unsigned int)wd[2] | ((unsigned int)wd[3] << 16);
        usrow[h_row][p0 + 2] = (unsigned int)wd[4] | ((unsigned int)wd[5] << 16);
    }

    // Barrier 2: presence flag AND the pre-H usrow barrier in one.
    const int any = __syncthreads_or((int)(bits != 0ULL));
    if (tid == 0 && any) atomicOr(&g_flags[m], 1);

    // Let kB launch its prologue now (its bufS1 reads are still gated by
    // cudaGridDependencySynchronize, which waits for kA full completion).
    cudaTriggerProgrammaticLaunchCompletion();

    // H min-plus via lane-pair DPX: p = lane pair (w=2p,2p+1); g16 owns
    // x in [g16*3, g16*3+3).
    const int p = tid % 24;
    const int g16 = tid / 24;
    unsigned int a0 = 0xFFFFFFFFu, a1 = 0xFFFFFFFFu, a2 = 0xFFFFFFFFu;

    #pragma unroll
    for (int j = 0; j < 48; j++) {
        unsigned int fj2 = usrow[j][p];
        uint4 q = *(const uint4*)&psqb[(j * 16 + g16) * 4];
        a0 = __viaddmin_u16x2(fj2, q.x, a0);
        a1 = __viaddmin_u16x2(fj2, q.y, a1);
        a2 = __viaddmin_u16x2(fj2, q.z, a2);
    }

    const int base = m * VOL + d * PLANE;
    const int x0 = g16 * 3;
    *(unsigned int*)&g_bufS1[base + x0 * 48 + 2 * p]       = a0;
    *(unsigned int*)&g_bufS1[base + (x0 + 1) * 48 + 2 * p] = a1;
    *(unsigned int*)&g_bufS1[base + (x0 + 2) * 48 + 2 * p] = a2;
}

// ---------------------------------------------------------------------------
// Kernel B: exact D min-plus via lane-pair DPX. One block per (m, h) plane
// (rows = d, cols = w), 384 threads. PDL: psqb fill before the dependency
// sync; bufS1 reads after it.
// ---------------------------------------------------------------------------
__global__ void __launch_bounds__(384) kB() {
    __shared__ unsigned int usrow[48][25];
    __shared__ unsigned int psqb[48 * 16 * 4];

    const int tid = threadIdx.x;
    const int m = blockIdx.x / 48;
    const int h = blockIdx.x - m * 48;
    const int base = m * VOL + h * 48;

    fill_psqb(psqb, tid);

    // Wait for kA's bufS1 to be complete and visible.
    cudaGridDependencySynchronize();

    {
        const unsigned int* src = (const unsigned int*)(g_bufS1 + base);
        #pragma unroll
        for (int k = 0; k < 3; k++) {
            int i = tid + k * 384;          // pair index 0..1151
            int dd = i / 24;
            int wp = i - dd * 24;
            usrow[dd][wp] = __ldg(&src[dd * (PLANE / 2) + wp]);
        }
    }
    __syncthreads();

    // Let k_loss start its pred/softmax prologue.
    cudaTriggerProgrammaticLaunchCompletion();

    const int p = tid % 24;
    const int g16 = tid / 24;
    unsigned int a0 = 0xFFFFFFFFu, a1 = 0xFFFFFFFFu, a2 = 0xFFFFFFFFu;

    #pragma unroll
    for (int j = 0; j < 48; j++) {
        unsigned int fj2 = usrow[j][p];
        uint4 q = *(const uint4*)&psqb[(j * 16 + g16) * 4];
        a0 = __viaddmin_u16x2(fj2, q.x, a0);
        a1 = __viaddmin_u16x2(fj2, q.y, a1);
        a2 = __viaddmin_u16x2(fj2, q.z, a2);
    }

    const int x0 = g16 * 3;
    *(unsigned int*)&g_bufS2[base + x0 * PLANE + 2 * p]       = a0;
    *(unsigned int*)&g_bufS2[base + (x0 + 1) * PLANE + 2 * p] = a1;
    *(unsigned int*)&g_bufS2[base + (x0 + 2) * PLANE + 2 * p] = a2;
}

// ---------------------------------------------------------------------------
// Loss: PDL prologue loads pred and computes softmax BEFORE the dependency
// sync (overlaps kB); after sync: dist loads, LUT gathers, dot, reduction.
// ---------------------------------------------------------------------------
__global__ void __launch_bounds__(256) k_loss(const float* __restrict__ pred,
                                              float* __restrict__ out) {
    const int t = blockIdx.x * 256 + threadIdx.x;   // 0..110591
    const int b = t / HV;
    const int r = t - b * HV;
    const int base2 = b * 4 * HV + r;

    const float2*  p2 = (const float2*)pred;
    const ushort2* q2 = (const ushort2*)g_bufS2;

    // ---- prologue (independent of kB): pred + softmax ----
    float2 P[4];
    #pragma unroll
    for (int c = 0; c < 4; c++) P[c] = __ldg(&p2[base2 + c * HV]);

    float ex[2][4], inv[2];
    #pragma unroll
    for (int v = 0; v < 2; v++) {
        float p0 = v ? P[0].y : P[0].x;
        float p1 = v ? P[1].y : P[1].x;
        float p2v = v ? P[2].y : P[2].x;
        float p3 = v ? P[3].y : P[3].x;
        float mx = fmaxf(fmaxf(p0, p1), fmaxf(p2v, p3));
        ex[v][0] = __expf(p0 - mx);
        ex[v][1] = __expf(p1 - mx);
        ex[v][2] = __expf(p2v - mx);
        ex[v][3] = __expf(p3 - mx);
        inv[v] = __fdividef(1.0f, ex[v][0] + ex[v][1] + ex[v][2] + ex[v][3]);
    }

    // ---- wait for kB's bufS2 (and transitively kA's flags/LUT) ----
    cudaGridDependencySynchronize();

    ushort2 Dv[4];
    #pragma unroll
    for (int c = 0; c < 4; c++) Dv[c] = __ldg(&q2[base2 + c * HV]);

    float fl[4];
    #pragma unroll
    for (int c = 0; c < 4; c++) fl[c] = g_flags[b * 4 + c] ? 1.0f : 0.0f;

    double sum = 0.0;
    #pragma unroll
    for (int v = 0; v < 2; v++) {
        int i0 = v ? Dv[0].y : Dv[0].x;
        int i1 = v ? Dv[1].y : Dv[1].x;
        int i2 = v ? Dv[2].y : Dv[2].x;
        int i3 = v ? Dv[3].y : Dv[3].x;

        float q0 = __ldg(&g_lut[i0]);
        float q1 = __ldg(&g_lut[i1]);
        float q2c = __ldg(&g_lut[i2]);
        float q3 = __ldg(&g_lut[i3]);

        float m01 = fminf(q0, q1), m23 = fminf(q2c, q3);
        float s0 = q0 + fminf(q1, m23);
        float s1 = q1 + fminf(q0, m23);
        float s2 = q2c + fminf(m01, q3);
        float s3 = q3 + fminf(m01, q2c);

        float local = fl[0] * ex[v][0] * s0 + fl[1] * ex[v][1] * s1
                    + fl[2] * ex[v][2] * s2 + fl[3] * ex[v][3] * s3;
        sum += (double)(local * inv[v]);
    }

    __shared__ double sh[256];
    __shared__ int islast;
    sh[threadIdx.x] = sum;
    __syncthreads();
    #pragma unroll
    for (int st = 128; st > 0; st >>= 1) {
        if (threadIdx.x < st) sh[threadIdx.x] += sh[threadIdx.x + st];
        __syncthreads();
    }
    if (threadIdx.x == 0) {
        g_partials[blockIdx.x] = sh[0];
        __threadfence();
        int done = atomicAdd(&g_count, 1);
        islast = (done == gridDim.x - 1);
    }
    __syncthreads();

    if (islast) {
        int i2n = threadIdx.x + 256;
        double v = g_partials[threadIdx.x]
                 + ((i2n < LOSSBLKS) ? g_partials[i2n] : 0.0);
        sh[threadIdx.x] = v;
        __syncthreads();
        #pragma unroll
        for (int st = 128; st > 0; st >>= 1) {
            if (threadIdx.x < st) sh[threadIdx.x] += sh[threadIdx.x + st];
            __syncthreads();
        }
        if (threadIdx.x == 0) {
            out[0] = (float)(sh[0] / (double)TOTALE);
            g_count = 0;                    // reset for next graph replay
        }
        if (threadIdx.x < 8) g_flags[threadIdx.x] = 0;
    }
}

// ---------------------------------------------------------------------------
extern "C" void kernel_launch(void* const* d_in, const int* in_sizes, int n_in,
                              void* d_out, int out_size) {
    const float* pred   = (const float*)d_in[0];
    const void*  target = d_in[1];
    float* out = (float*)d_out;

    kA<<<8 * 48, 384>>>(target);

    cudaLaunchAttribute at[1];
    at[0].id = cudaLaunchAttributeProgrammaticStreamSerialization;
    at[0].val.programmaticStreamSerializationAllowed = 1;

    cudaLaunchConfig_t cfgB = {};
    cfgB.gridDim = dim3(8 * 48);
    cfgB.blockDim = dim3(384);
    cfgB.attrs = at;
    cfgB.numAttrs = 1;
    cudaLaunchKernelEx(&cfgB, kB);

    cudaLaunchConfig_t cfgL = {};
    cfgL.gridDim = dim3(LOSSBLKS);
    cfgL.blockDim = dim3(256);
    cfgL.attrs = at;
    cfgL.numAttrs = 1;
    cudaLaunchKernelEx(&cfgL, k_loss, pred, out);
}

// round 17
// speedup vs baseline: 1.3902x; 1.0960x over previous
#include <cuda_runtime.h>
#include <math.h>

#define VOL    110592   // 48*48*48
#define PLANE  2304     // 48*48
#define TOTALE 884736   // B*C*VOL
#define U16INF 50000    // u16 'infinity'; max transient 50000+2209 < 65535
#define NBLK2  384      // fused kernel blocks: 2*48*4 (b, h, d-quarter)

// Static scratch (no allocations allowed)
__device__ unsigned short g_bufS1[8 * VOL];  // pos^2 after W+H (u16)
__device__ float  g_lut[65536];              // sqrt LUT, full u16 range
__device__ int    g_flags[8];   // zero-init; reset by epilogue each replay
__device__ int    g_count;      // zero-init; reset by epilogue
__device__ double g_partials[NBLK2];

// psqb table: entry ((j*16 + g16)*4 + kk), kk<3 used: x = g16*3 + kk;
// value = (x-j)^2 broadcast into both u16 halves. 48*16*4 u32 = 12 KB.
__device__ __forceinline__ void fill_psqb(unsigned int* psqb, int tid) {
    for (int i = tid; i < 48 * 16 * 4; i += 384) {
        int j   = i >> 6;
        int g16 = (i >> 2) & 15;
        int kk  = i & 3;
        unsigned int val = 0;
        if (kk < 3) {
            int dx = g16 * 3 + kk - j;
            val = (unsigned int)(dx * dx) * 0x00010001u;
        }
        psqb[i] = val;
    }
}

// ---------------------------------------------------------------------------
// Kernel A (round-15 champion): one block per (m=b*4+c, d) plane, 384 thr.
// Speculative int32 label load; dtype detect overlapped; row masks via
// shfl_xor; W-EDT via clz/ffs; H min-plus via lane-pair DPX.
// Blocks 0..15 fill the sqrt LUT.
// ---------------------------------------------------------------------------
__global__ void __launch_bounds__(384) kA(const void* __restrict__ target) {
    __shared__ unsigned int usrow[48][25];
    __shared__ unsigned int psqb[48 * 16 * 4];

    const int tid = threadIdx.x;
    const int m = blockIdx.x / 48;        // b*4 + c
    const int d = blockIdx.x - m * 48;
    const int b = m >> 2;
    const int c = m & 3;
    const int ebase = b * VOL + d * PLANE + tid * 6;

    // Speculative int32 label load (in-bounds for both dtypes).
    const int2* tp32 = (const int2*)((const int*)target + ebase);
    int2 s0 = __ldg(&tp32[0]);
    int2 s1 = __ldg(&tp32[1]);
    int2 s2 = __ldg(&tp32[2]);

    bool bad = false;
    if (tid < 64) {
        long long v = ((const long long*)target)[tid];
        bad = (v < 0 || v > 3);
    }

    fill_psqb(psqb, tid);

    if (blockIdx.x < 16) {
        const int lbase = blockIdx.x * 4096;
        #pragma unroll
        for (int k = 0; k < 11; k++) {
            int i = tid + k * 384;
            if (i < 4096) g_lut[lbase + i] = sqrtf((float)(lbase + i));
        }
    }

    const bool is64 = !__syncthreads_or((int)bad);

    unsigned char lb[6];
    if (is64) {
        const longlong2* tp = (const longlong2*)((const long long*)target + ebase);
        longlong2 v0 = __ldg(&tp[0]);
        longlong2 v1 = __ldg(&tp[1]);
        longlong2 v2 = __ldg(&tp[2]);
        lb[0] = (unsigned char)v0.x; lb[1] = (unsigned char)v0.y;
        lb[2] = (unsigned char)v1.x; lb[3] = (unsigned char)v1.y;
        lb[4] = (unsigned char)v2.x; lb[5] = (unsigned char)v2.y;
    } else {
        lb[0] = (unsigned char)s0.x; lb[1] = (unsigned char)s0.y;
        lb[2] = (unsigned char)s1.x; lb[3] = (unsigned char)s1.y;
        lb[4] = (unsigned char)s2.x; lb[5] = (unsigned char)s2.y;
    }

    const int w0 = (tid & 7) * 6;
    unsigned long long bits = 0ULL;
    #pragma unroll
    for (int k = 0; k < 6; k++) {
        unsigned long long isc = (unsigned long long)(lb[k] == (unsigned char)c);
        bits |= isc << (w0 + k);
    }
    unsigned long long mm = bits;
    mm |= __shfl_xor_sync(0xffffffffu, mm, 1, 8);
    mm |= __shfl_xor_sync(0xffffffffu, mm, 2, 8);
    mm |= __shfl_xor_sync(0xffffffffu, mm, 4, 8);

    {
        unsigned short wd[6];
        #pragma unroll
        for (int k = 0; k < 6; k++) {
            int ww = w0 + k;
            unsigned long long lowm = mm << (63 - ww);
            unsigned long long him  = mm >> ww;
            int dl = lowm ? __clzll(lowm) : 99;
            int dr = him ? (__ffsll(him) - 1) : 99;
            int dd = min(dl, dr);
            wd[k] = (dd <= 47) ? (unsigned short)(dd * dd)
                               : (unsigned short)U16INF;
        }
        const int h_row = tid >> 3;
        const int p0 = (tid & 7) * 3;
        usrow[h_row][p0]     = (unsigned int)wd[0] | ((unsigned int)wd[1] << 16);
        usrow[h_row][p0 + 1] = (unsigned int)wd[2] | ((unsigned int)wd[3] << 16);
        usrow[h_row][p0 + 2] = (unsigned int)wd[4] | ((unsigned int)wd[5] << 16);
    }

    const int any = __syncthreads_or((int)(bits != 0ULL));
    if (tid == 0 && any) atomicOr(&g_flags[m], 1);

    const int p = tid % 24;
    const int g16 = tid / 24;
    unsigned int a0 = 0xFFFFFFFFu, a1 = 0xFFFFFFFFu, a2 = 0xFFFFFFFFu;

    #pragma unroll
    for (int j = 0; j < 48; j++) {
        unsigned int fj2 = usrow[j][p];
        uint4 q = *(const uint4*)&psqb[(j * 16 + g16) * 4];
        a0 = __viaddmin_u16x2(fj2, q.x, a0);
        a1 = __viaddmin_u16x2(fj2, q.y, a1);
        a2 = __viaddmin_u16x2(fj2, q.z, a2);
    }

    const int base = m * VOL + d * PLANE;
    const int x0 = g16 * 3;
    *(unsigned int*)&g_bufS1[base + x0 * 48 + 2 * p]       = a0;
    *(unsigned int*)&g_bufS1[base + (x0 + 1) * 48 + 2 * p] = a1;
    *(unsigned int*)&g_bufS1[base + (x0 + 2) * 48 + 2 * p] = a2;
}

// ---------------------------------------------------------------------------
// Fused kernel B+loss: block = (b, h, d-quarter q), 384 blocks x 384 thr.
// Loads the FULL 4-class (d,w) input plane for (b,h) (4x redundant; DRAM
// idle), prefetches pred + computes softmax (independent), D min-plus via
// lane-pair DPX for the block's 12 output d-values x 4 classes, then the
// loss for its 576 voxels from smem. Deterministic reduction; last block
// finishes and resets globals.
// ---------------------------------------------------------------------------
__global__ void __launch_bounds__(384) kBL(const float* __restrict__ pred,
                                           float* __restrict__ out) {
    __shared__ unsigned int uin[4 * 48 * 25];   // input planes, row stride 25
    __shared__ unsigned int sD[4 * 12 * 25];    // output quarter, row stride 25
    __shared__ unsigned int psqb[48 * 16 * 4];
    __shared__ double sh[384];
    __shared__ int islast;

    const int tid = threadIdx.x;
    const int bq = blockIdx.x;          // ((b*48 + h)*4 + q)
    const int b = bq / 192;
    const int rem = bq - b * 192;
    const int h = rem >> 2;
    const int q = rem & 3;

    // ---- issue all global loads up front ----
    // input planes: 4 classes x 1152 u32 words, 12 per thread.
    unsigned int rv[12];
    #pragma unroll
    for (int k = 0; k < 12; k++) {
        int idx = tid + k * 384;        // 0..4607
        int cls = idx / 1152;
        int r = idx - cls * 1152;
        int dd = r / 24;
        int wp = r - dd * 24;
        const unsigned int* src =
            (const unsigned int*)(g_bufS1 + (b * 4 + cls) * VOL + h * 48);
        rv[k] = __ldg(&src[dd * (PLANE / 2) + wp]);
    }

    // pred for this thread's 2 loss voxels (i = tid, tid+384; i<576).
    // voxel i: d = q*12 + i/48, w = i%48.
    float Pv[2][4];
    const int i0 = tid;
    const int i1 = tid + 384;
    const bool v1ok = (i1 < 576);
    {
        int dl0 = i0 / 48, w_0 = i0 - dl0 * 48;
        int off0 = b * 4 * VOL + (q * 12 + dl0) * PLANE + h * 48 + w_0;
        #pragma unroll
        for (int c = 0; c < 4; c++) Pv[0][c] = __ldg(&pred[off0 + c * VOL]);
        int dl1 = i1 / 48, w_1 = i1 - dl1 * 48;
        int off1 = b * 4 * VOL + (q * 12 + dl1) * PLANE + h * 48 + w_1;
        #pragma unroll
        for (int c = 0; c < 4; c++)
            Pv[1][c] = v1ok ? __ldg(&pred[off1 + c * VOL]) : 0.0f;
    }

    float fl[4];
    #pragma unroll
    for (int c = 0; c < 4; c++) fl[c] = g_flags[b * 4 + c] ? 1.0f : 0.0f;

    fill_psqb(psqb, tid);

    // softmax (independent of distances)
    float ex[2][4], inv[2];
    #pragma unroll
    for (int v = 0; v < 2; v++) {
        float mx = fmaxf(fmaxf(Pv[v][0], Pv[v][1]), fmaxf(Pv[v][2], Pv[v][3]));
        #pragma unroll
        for (int c = 0; c < 4; c++) ex[v][c] = __expf(Pv[v][c] - mx);
        inv[v] = __fdividef(1.0f, ex[v][0] + ex[v][1] + ex[v][2] + ex[v][3]);
    }

    // park loaded plane words into smem
    #pragma unroll
    for (int k = 0; k < 12; k++) {
        int idx = tid + k * 384;
        int cls = idx / 1152;
        int r = idx - cls * 1152;
        int dd = r / 24;
        int wp = r - dd * 24;
        uin[cls * 1200 + dd * 25 + wp] = rv[k];
    }
    __syncthreads();

    // ---- D min-plus for this quarter: thread = (cls, gq, p) ----
    const int cls = tid / 96;
    const int t96 = tid - cls * 96;
    const int gq = t96 / 24;            // 0..3 within quarter
    const int p = t96 - gq * 24;        // lane pair
    const int g16 = q * 4 + gq;         // global x-group

    unsigned int a0 = 0xFFFFFFFFu, a1 = 0xFFFFFFFFu, a2 = 0xFFFFFFFFu;
    const unsigned int* myplane = &uin[cls * 1200];
    #pragma unroll
    for (int j = 0; j < 48; j++) {
        unsigned int fj2 = myplane[j * 25 + p];
        uint4 qv = *(const uint4*)&psqb[(j * 16 + g16) * 4];
        a0 = __viaddmin_u16x2(fj2, qv.x, a0);
        a1 = __viaddmin_u16x2(fj2, qv.y, a1);
        a2 = __viaddmin_u16x2(fj2, qv.z, a2);
    }
    {
        const int xl = gq * 3;          // local x (d) within quarter
        sD[cls * 300 + xl * 25 + p]       = a0;
        sD[cls * 300 + (xl + 1) * 25 + p] = a1;
        sD[cls * 300 + (xl + 2) * 25 + p] = a2;
    }
    __syncthreads();

    // ---- loss for this block's 576 voxels ----
    const unsigned short* sDu = (const unsigned short*)sD;
    double sum = 0.0;
    #pragma unroll
    for (int v = 0; v < 2; v++) {
        int i = tid + v * 384;
        if (v == 1 && !v1ok) break;
        int dl = i / 48, w = i - dl * 48;
        float qv[4];
        #pragma unroll
        for (int c = 0; c < 4; c++) {
            unsigned short dv = sDu[(c * 300 + dl * 25) * 2 + w];
            qv[c] = __ldg(&g_lut[dv]);
        }
        float m01 = fminf(qv[0], qv[1]), m23 = fminf(qv[2], qv[3]);
        float s0 = qv[0] + fminf(qv[1], m23);
        float s1 = qv[1] + fminf(qv[0], m23);
        float s2 = qv[2] + fminf(m01, qv[3]);
        float s3 = qv[3] + fminf(m01, qv[2]);
        float local = fl[0] * ex[v][0] * s0 + fl[1] * ex[v][1] * s1
                    + fl[2] * ex[v][2] * s2 + fl[3] * ex[v][3] * s3;
        sum += (double)(local * inv[v]);
    }

    // ---- deterministic reduction: 384 -> 128 (3-way) -> tree ----
    sh[tid] = sum;
    __syncthreads();
    if (tid < 128) sh[tid] += sh[tid + 128] + sh[tid + 256];
    __syncthreads();
    #pragma unroll
    for (int st = 64; st > 0; st >>= 1) {
        if (tid < st) sh[tid] += sh[tid + st];
        __syncthreads();
    }
    if (tid == 0) {
        g_partials[bq] = sh[0];
        __threadfence();
        int done = atomicAdd(&g_count, 1);
        islast = (done == NBLK2 - 1);
    }
    __syncthreads();

    if (islast) {
        if (tid < 128)
            sh[tid] = g_partials[tid] + g_partials[tid + 128] + g_partials[tid + 256];
        __syncthreads();
        #pragma unroll
        for (int st = 64; st > 0; st >>= 1) {
            if (tid < st) sh[tid] += sh[tid + st];
            __syncthreads();
        }
        if (tid == 0) {
            out[0] = (float)(sh[0] / (double)TOTALE);
            g_count = 0;                // reset for next graph replay
        }
        if (tid < 8) g_flags[tid] = 0;
    }
}

// ---------------------------------------------------------------------------
extern "C" void kernel_launch(void* const* d_in, const int* in_sizes, int n_in,
                              void* d_out, int out_size) {
    const float* pred   = (const float*)d_in[0];
    const void*  target = d_in[1];
    float* out = (float*)d_out;

    kA<<<8 * 48, 384>>>(target);        // W bit-scan + H lane-pair DPX
    kBL<<<NBLK2, 384>>>(pred, out);     // D DPX + fused loss + reduction
}